// round 15
// baseline (speedup 1.0000x reference)
#include <cuda_runtime.h>
#include <cuda_fp16.h>
#include <cuda_bf16.h>
#include <stdint.h>

// GCN: out[n,:] = sum_{e: dst[e]==n} w[e] * data[src[e],:] @ theta
// project-first (proj = data@theta in fp16), bucket-build, gather-reduce.
// R14: GEMM restructured to 4-k chunks with LDS.128 on both operands
// (smem wavefronts 8/k -> 3/k per warp); gather moves to 8 lanes/node with
// LDG.128 proj reads and FFMA2 accumulation.
//
// Shapes (fixed): N = 100000, E = 1200000, D = 64.

#define D 64
#define MAX_NODES 100096
#define CAP 64            // per-node bucket capacity; Poisson(12) max-deg ~40
#define OVF_CAP 32768     // overflow safety net (normally empty)

// Static device scratch (no runtime allocation).
__device__ __half g_projh[(size_t)MAX_NODES * D];        // 12.8 MB (L2-resident)
__device__ int2   g_bucket[(size_t)MAX_NODES * CAP];     // {src, w_bits}
__device__ int    g_cnt[MAX_NODES + 1];                  // [MAX_NODES] = ovf count
__device__ int    g_ovf_list[OVF_CAP];

// ---- packed f32x2 helpers (Blackwell FFMA2; only reachable via PTX) -------
__device__ __forceinline__ unsigned long long pk2(float lo, float hi) {
    unsigned long long r;
    asm("mov.b64 %0, {%1, %2};" : "=l"(r) : "f"(lo), "f"(hi));
    return r;
}
__device__ __forceinline__ void upk2(float& lo, float& hi, unsigned long long v) {
    asm("mov.b64 {%0, %1}, %2;" : "=f"(lo), "=f"(hi) : "l"(v));
}
__device__ __forceinline__ void ffma2(unsigned long long& acc,
                                      unsigned long long a,
                                      unsigned long long b) {
    asm("fma.rn.f32x2 %0, %1, %2, %0;" : "+l"(acc) : "l"(a), "l"(b));
}

// ---------------------------------------------------------------------------
// Kernel 1: proj[N,64] = fp16( data[N,64] @ theta[64,64] )
// 256 threads, 64x64 tile, 4x4 register tile / thread.
// k processed in chunks of 4 so BOTH smem operands use LDS.128:
//   data:  4 x LDS.128 per 4-k (2 unique addrs/warp -> 1 wavefront each)
//   theta: 4 x LDS.128 per 4-k (256B/warp -> 2 wavefronts each)
// = 3 wavefronts per k per warp (was 8).
// ---------------------------------------------------------------------------
__global__ __launch_bounds__(256)
void proj_kernel(const float* __restrict__ data,
                 const float* __restrict__ theta,
                 __half* __restrict__ proj,
                 int N)
{
    __shared__ float sTheta[D * D];   // [k][c]
    __shared__ float sData[64 * D];   // [r][k]

    const int tid = threadIdx.x;
    const int rowBase = blockIdx.x * 64;

    {
        const float4* t4 = reinterpret_cast<const float4*>(theta);
        float4* st4 = reinterpret_cast<float4*>(sTheta);
        #pragma unroll
        for (int i = 0; i < 4; i++)
            st4[tid + i * 256] = t4[tid + i * 256];
    }
    {
        float4* sd4 = reinterpret_cast<float4*>(sData);
        const float4* g4 = reinterpret_cast<const float4*>(data);
        #pragma unroll
        for (int i = 0; i < 4; i++) {
            int idx = tid + i * 256;
            int r = idx >> 4;
            int gr = rowBase + r;
            float4 v = make_float4(0.f, 0.f, 0.f, 0.f);
            if (gr < N) v = g4[(size_t)gr * (D / 4) + (idx & 15)];
            sd4[idx] = v;
        }
    }
    __syncthreads();

    const int ty = tid >> 4;   // rows ty*4..+3
    const int tx = tid & 15;   // cols tx*4..+3 (2 packed col-pairs)

    unsigned long long acc2[4][2];
    #pragma unroll
    for (int i = 0; i < 4; i++) { acc2[i][0] = 0ull; acc2[i][1] = 0ull; }

    #pragma unroll 4
    for (int k0 = 0; k0 < D; k0 += 4) {
        // 4 theta rows, this thread's 4 columns: LDS.128 each.
        float4 b[4];
        #pragma unroll
        for (int j = 0; j < 4; j++)
            b[j] = *reinterpret_cast<const float4*>(&sTheta[(k0 + j) * D + tx * 4]);

        // 4 data rows, k-slice [k0, k0+4): LDS.128 each (2 unique addrs/warp).
        float4 a[4];
        #pragma unroll
        for (int i = 0; i < 4; i++)
            a[i] = *reinterpret_cast<const float4*>(&sData[(ty * 4 + i) * D + k0]);

        #pragma unroll
        for (int j = 0; j < 4; j++) {
            unsigned long long b01 = pk2(b[j].x, b[j].y);
            unsigned long long b23 = pk2(b[j].z, b[j].w);
            #pragma unroll
            for (int i = 0; i < 4; i++) {
                float av = (j == 0) ? a[i].x : (j == 1) ? a[i].y
                         : (j == 2) ? a[i].z : a[i].w;
                unsigned long long aa = pk2(av, av);
                ffma2(acc2[i][0], aa, b01);
                ffma2(acc2[i][1], aa, b23);
            }
        }
    }

    #pragma unroll
    for (int i = 0; i < 4; i++) {
        int gr = rowBase + ty * 4 + i;
        if (gr < N) {
            float c0, c1, c2, c3;
            upk2(c0, c1, acc2[i][0]);
            upk2(c2, c3, acc2[i][1]);
            __half2 h01 = __floats2half2_rn(c0, c1);
            __half2 h23 = __floats2half2_rn(c2, c3);
            uint2 pkd;
            pkd.x = *reinterpret_cast<unsigned*>(&h01);
            pkd.y = *reinterpret_cast<unsigned*>(&h23);
            *reinterpret_cast<uint2*>(&proj[(size_t)gr * D + tx * 4]) = pkd;
        }
    }
}

// ---------------------------------------------------------------------------
// Kernel 2: bucket build (1.2M scalar atomics + scattered 8B stores).
// ---------------------------------------------------------------------------
__global__ __launch_bounds__(256)
void fill_kernel(const int* __restrict__ src, const int* __restrict__ dst,
                 const float* __restrict__ w, int E)
{
    int e = blockIdx.x * blockDim.x + threadIdx.x;
    if (e >= E) return;
    int d = dst[e];
    int pos = atomicAdd(&g_cnt[d], 1);
    if (pos < CAP) {
        g_bucket[((size_t)d << 6) + pos] = make_int2(src[e], __float_as_int(w[e]));
    } else {
        int op = atomicAdd(&g_cnt[MAX_NODES], 1);
        if (op < OVF_CAP) g_ovf_list[op] = e;
    }
}

// ---------------------------------------------------------------------------
// Kernel 3: gather-reduce. 8 lanes per node; lane `part` owns 8 output
// columns (one uint4 = 8 fp16 of the 128B proj row). fp32 accumulation via
// FFMA2 packed pairs. Unroll-2 for MLP. One coalesced store pair per lane.
// ---------------------------------------------------------------------------
__device__ __forceinline__ void acc_edge(unsigned long long acc[4],
                                         uint4 v, unsigned long long wpair)
{
    float2 f0 = __half22float2(*reinterpret_cast<__half2*>(&v.x));
    float2 f1 = __half22float2(*reinterpret_cast<__half2*>(&v.y));
    float2 f2 = __half22float2(*reinterpret_cast<__half2*>(&v.z));
    float2 f3 = __half22float2(*reinterpret_cast<__half2*>(&v.w));
    ffma2(acc[0], wpair, pk2(f0.x, f0.y));
    ffma2(acc[1], wpair, pk2(f1.x, f1.y));
    ffma2(acc[2], wpair, pk2(f2.x, f2.y));
    ffma2(acc[3], wpair, pk2(f3.x, f3.y));
}

__global__ __launch_bounds__(256)
void gather_kernel(const int* __restrict__ src, const int* __restrict__ dst,
                   const float* __restrict__ w, float* __restrict__ out, int N)
{
    int gid = blockIdx.x * blockDim.x + threadIdx.x;
    int n = gid >> 3;
    if (n >= N) return;
    int part = gid & 7;   // uint4 index within the 128B row

    int craw = g_cnt[n];
    int c = craw > CAP ? CAP : craw;

    const int2* bk = g_bucket + ((size_t)n << 6);
    const uint4* p4 = reinterpret_cast<const uint4*>(g_projh);  // 8 uint4 / row

    unsigned long long acc0[4] = {0ull, 0ull, 0ull, 0ull};
    unsigned long long acc1[4] = {0ull, 0ull, 0ull, 0ull};

    int i = 0;
    for (; i + 2 <= c; i += 2) {
        int2 e0 = bk[i];
        int2 e1 = bk[i + 1];
        uint4 v0 = p4[(size_t)e0.x * 8 + part];
        uint4 v1 = p4[(size_t)e1.x * 8 + part];
        float w0 = __int_as_float(e0.y);
        float w1 = __int_as_float(e1.y);
        acc_edge(acc0, v0, pk2(w0, w0));
        acc_edge(acc1, v1, pk2(w1, w1));
    }
    if (i < c) {
        int2 e0 = bk[i];
        uint4 v0 = p4[(size_t)e0.x * 8 + part];
        float w0 = __int_as_float(e0.y);
        acc_edge(acc0, v0, pk2(w0, w0));
    }

    // Overflow path: never taken for this dataset, keeps correctness
    // unconditional for any degree distribution.
    if (craw > CAP) {
        int m = g_cnt[MAX_NODES];
        if (m > OVF_CAP) m = OVF_CAP;
        for (int j = 0; j < m; j++) {
            int e = g_ovf_list[j];
            if (dst[e] == n) {
                float we = w[e];
                uint4 v = p4[(size_t)src[e] * 8 + part];
                acc_edge(acc0, v, pk2(we, we));
            }
        }
    }

    float r[8];
    #pragma unroll
    for (int q = 0; q < 4; q++) {
        float lo0, hi0, lo1, hi1;
        upk2(lo0, hi0, acc0[q]);
        upk2(lo1, hi1, acc1[q]);
        r[q * 2 + 0] = lo0 + lo1;
        r[q * 2 + 1] = hi0 + hi1;
    }
    float4* o4 = reinterpret_cast<float4*>(out + (size_t)n * D + part * 8);
    o4[0] = make_float4(r[0], r[1], r[2], r[3]);
    o4[1] = make_float4(r[4], r[5], r[6], r[7]);
}

// ---------------------------------------------------------------------------
// kernel_launch — graph-capturable, allocation-free.
// Fork: GEMM on s1 concurrent with memset(cnt)+fill on the main stream.
// Input order: src[E] i32, dst[E] i32, w[E] f32, data[N*64] f32,
//              theta[64*64] f32, num_nodes i32
// ---------------------------------------------------------------------------
extern "C" void kernel_launch(void* const* d_in, const int* in_sizes, int n_in,
                              void* d_out, int out_size)
{
    const int*   src   = (const int*)  d_in[0];
    const int*   dst   = (const int*)  d_in[1];
    const float* w     = (const float*)d_in[2];
    const float* data  = (const float*)d_in[3];
    const float* theta = (const float*)d_in[4];

    const int E = in_sizes[0];
    const int N = in_sizes[3] / D;

    float* out = (float*)d_out;

    static __half* proj_ptr = nullptr;
    static int*    cnt_ptr  = nullptr;
    static cudaStream_t s1 = nullptr;
    static cudaEvent_t evFork = nullptr, evJoin = nullptr;
    if (!proj_ptr) {
        void* p = nullptr;
        cudaGetSymbolAddress(&p, g_projh); proj_ptr = (__half*)p;
        cudaGetSymbolAddress(&p, g_cnt);   cnt_ptr  = (int*)p;
        cudaStreamCreateWithFlags(&s1, cudaStreamNonBlocking);
        cudaEventCreateWithFlags(&evFork, cudaEventDisableTiming);
        cudaEventCreateWithFlags(&evJoin, cudaEventDisableTiming);
    }

    // Fork: GEMM on s1 (independent of the edge arrays).
    cudaEventRecord(evFork, 0);
    cudaStreamWaitEvent(s1, evFork, 0);
    int gemmBlocks = (N + 63) / 64;
    proj_kernel<<<gemmBlocks, 256, 0, s1>>>(data, theta, proj_ptr, N);
    cudaEventRecord(evJoin, s1);

    // Main stream: reset counters (+ ovf counter), build buckets.
    cudaMemsetAsync(cnt_ptr, 0, (size_t)(MAX_NODES + 1) * sizeof(int), 0);
    int fillBlocks = (E + 255) / 256;
    fill_kernel<<<fillBlocks, 256>>>(src, dst, w, E);

    // Join, then gather-reduce (writes every output row; no out memset).
    cudaStreamWaitEvent(0, evJoin, 0);
    long long gthreads = (long long)N * 8;
    int gatherBlocks = (int)((gthreads + 255) / 256);
    gather_kernel<<<gatherBlocks, 256>>>(src, dst, w, out, N);
}

// round 16
// speedup vs baseline: 1.0046x; 1.0046x over previous
#include <cuda_runtime.h>
#include <cuda_fp16.h>
#include <cuda_bf16.h>
#include <stdint.h>

// GCN: out[n,:] = sum_{e: dst[e]==n} w[e] * data[src[e],:] @ theta
// project-first (proj = data@theta in fp16), bucket-build, gather-reduce.
// R14: GEMM restructured to 4-k chunks with LDS.128 on both operands
// (smem wavefronts 8/k -> 3/k per warp); gather moves to 8 lanes/node with
// LDG.128 proj reads and FFMA2 accumulation.
//
// Shapes (fixed): N = 100000, E = 1200000, D = 64.

#define D 64
#define MAX_NODES 100096
#define CAP 64            // per-node bucket capacity; Poisson(12) max-deg ~40
#define OVF_CAP 32768     // overflow safety net (normally empty)

// Static device scratch (no runtime allocation).
__device__ __half g_projh[(size_t)MAX_NODES * D];        // 12.8 MB (L2-resident)
__device__ int2   g_bucket[(size_t)MAX_NODES * CAP];     // {src, w_bits}
__device__ int    g_cnt[MAX_NODES + 1];                  // [MAX_NODES] = ovf count
__device__ int    g_ovf_list[OVF_CAP];

// ---- packed f32x2 helpers (Blackwell FFMA2; only reachable via PTX) -------
__device__ __forceinline__ unsigned long long pk2(float lo, float hi) {
    unsigned long long r;
    asm("mov.b64 %0, {%1, %2};" : "=l"(r) : "f"(lo), "f"(hi));
    return r;
}
__device__ __forceinline__ void upk2(float& lo, float& hi, unsigned long long v) {
    asm("mov.b64 {%0, %1}, %2;" : "=f"(lo), "=f"(hi) : "l"(v));
}
__device__ __forceinline__ void ffma2(unsigned long long& acc,
                                      unsigned long long a,
                                      unsigned long long b) {
    asm("fma.rn.f32x2 %0, %1, %2, %0;" : "+l"(acc) : "l"(a), "l"(b));
}

// ---------------------------------------------------------------------------
// Kernel 1: proj[N,64] = fp16( data[N,64] @ theta[64,64] )
// 256 threads, 64x64 tile, 4x4 register tile / thread.
// k processed in chunks of 4 so BOTH smem operands use LDS.128:
//   data:  4 x LDS.128 per 4-k (2 unique addrs/warp -> 1 wavefront each)
//   theta: 4 x LDS.128 per 4-k (256B/warp -> 2 wavefronts each)
// = 3 wavefronts per k per warp (was 8).
// ---------------------------------------------------------------------------
__global__ __launch_bounds__(256)
void proj_kernel(const float* __restrict__ data,
                 const float* __restrict__ theta,
                 __half* __restrict__ proj,
                 int N)
{
    __shared__ float sTheta[D * D];   // [k][c]
    __shared__ float sData[64 * D];   // [r][k]

    const int tid = threadIdx.x;
    const int rowBase = blockIdx.x * 64;

    {
        const float4* t4 = reinterpret_cast<const float4*>(theta);
        float4* st4 = reinterpret_cast<float4*>(sTheta);
        #pragma unroll
        for (int i = 0; i < 4; i++)
            st4[tid + i * 256] = t4[tid + i * 256];
    }
    {
        float4* sd4 = reinterpret_cast<float4*>(sData);
        const float4* g4 = reinterpret_cast<const float4*>(data);
        #pragma unroll
        for (int i = 0; i < 4; i++) {
            int idx = tid + i * 256;
            int r = idx >> 4;
            int gr = rowBase + r;
            float4 v = make_float4(0.f, 0.f, 0.f, 0.f);
            if (gr < N) v = g4[(size_t)gr * (D / 4) + (idx & 15)];
            sd4[idx] = v;
        }
    }
    __syncthreads();

    const int ty = tid >> 4;   // rows ty*4..+3
    const int tx = tid & 15;   // cols tx*4..+3 (2 packed col-pairs)

    unsigned long long acc2[4][2];
    #pragma unroll
    for (int i = 0; i < 4; i++) { acc2[i][0] = 0ull; acc2[i][1] = 0ull; }

    #pragma unroll 4
    for (int k0 = 0; k0 < D; k0 += 4) {
        // 4 theta rows, this thread's 4 columns: LDS.128 each.
        float4 b[4];
        #pragma unroll
        for (int j = 0; j < 4; j++)
            b[j] = *reinterpret_cast<const float4*>(&sTheta[(k0 + j) * D + tx * 4]);

        // 4 data rows, k-slice [k0, k0+4): LDS.128 each (2 unique addrs/warp).
        float4 a[4];
        #pragma unroll
        for (int i = 0; i < 4; i++)
            a[i] = *reinterpret_cast<const float4*>(&sData[(ty * 4 + i) * D + k0]);

        #pragma unroll
        for (int j = 0; j < 4; j++) {
            unsigned long long b01 = pk2(b[j].x, b[j].y);
            unsigned long long b23 = pk2(b[j].z, b[j].w);
            #pragma unroll
            for (int i = 0; i < 4; i++) {
                float av = (j == 0) ? a[i].x : (j == 1) ? a[i].y
                         : (j == 2) ? a[i].z : a[i].w;
                unsigned long long aa = pk2(av, av);
                ffma2(acc2[i][0], aa, b01);
                ffma2(acc2[i][1], aa, b23);
            }
        }
    }

    #pragma unroll
    for (int i = 0; i < 4; i++) {
        int gr = rowBase + ty * 4 + i;
        if (gr < N) {
            float c0, c1, c2, c3;
            upk2(c0, c1, acc2[i][0]);
            upk2(c2, c3, acc2[i][1]);
            __half2 h01 = __floats2half2_rn(c0, c1);
            __half2 h23 = __floats2half2_rn(c2, c3);
            uint2 pkd;
            pkd.x = *reinterpret_cast<unsigned*>(&h01);
            pkd.y = *reinterpret_cast<unsigned*>(&h23);
            *reinterpret_cast<uint2*>(&proj[(size_t)gr * D + tx * 4]) = pkd;
        }
    }
}

// ---------------------------------------------------------------------------
// Kernel 2: bucket build (1.2M scalar atomics + scattered 8B stores).
// ---------------------------------------------------------------------------
__global__ __launch_bounds__(256)
void fill_kernel(const int* __restrict__ src, const int* __restrict__ dst,
                 const float* __restrict__ w, int E)
{
    int e = blockIdx.x * blockDim.x + threadIdx.x;
    if (e >= E) return;
    int d = dst[e];
    int pos = atomicAdd(&g_cnt[d], 1);
    if (pos < CAP) {
        g_bucket[((size_t)d << 6) + pos] = make_int2(src[e], __float_as_int(w[e]));
    } else {
        int op = atomicAdd(&g_cnt[MAX_NODES], 1);
        if (op < OVF_CAP) g_ovf_list[op] = e;
    }
}

// ---------------------------------------------------------------------------
// Kernel 3: gather-reduce. 8 lanes per node; lane `part` owns 8 output
// columns (one uint4 = 8 fp16 of the 128B proj row). fp32 accumulation via
// FFMA2 packed pairs. Unroll-2 for MLP. One coalesced store pair per lane.
// ---------------------------------------------------------------------------
__device__ __forceinline__ void acc_edge(unsigned long long acc[4],
                                         uint4 v, unsigned long long wpair)
{
    float2 f0 = __half22float2(*reinterpret_cast<__half2*>(&v.x));
    float2 f1 = __half22float2(*reinterpret_cast<__half2*>(&v.y));
    float2 f2 = __half22float2(*reinterpret_cast<__half2*>(&v.z));
    float2 f3 = __half22float2(*reinterpret_cast<__half2*>(&v.w));
    ffma2(acc[0], wpair, pk2(f0.x, f0.y));
    ffma2(acc[1], wpair, pk2(f1.x, f1.y));
    ffma2(acc[2], wpair, pk2(f2.x, f2.y));
    ffma2(acc[3], wpair, pk2(f3.x, f3.y));
}

__global__ __launch_bounds__(256)
void gather_kernel(const int* __restrict__ src, const int* __restrict__ dst,
                   const float* __restrict__ w, float* __restrict__ out, int N)
{
    int gid = blockIdx.x * blockDim.x + threadIdx.x;
    int n = gid >> 3;
    if (n >= N) return;
    int part = gid & 7;   // uint4 index within the 128B row

    int craw = g_cnt[n];
    int c = craw > CAP ? CAP : craw;

    const int2* bk = g_bucket + ((size_t)n << 6);
    const uint4* p4 = reinterpret_cast<const uint4*>(g_projh);  // 8 uint4 / row

    unsigned long long acc0[4] = {0ull, 0ull, 0ull, 0ull};
    unsigned long long acc1[4] = {0ull, 0ull, 0ull, 0ull};

    int i = 0;
    for (; i + 2 <= c; i += 2) {
        int2 e0 = bk[i];
        int2 e1 = bk[i + 1];
        uint4 v0 = p4[(size_t)e0.x * 8 + part];
        uint4 v1 = p4[(size_t)e1.x * 8 + part];
        float w0 = __int_as_float(e0.y);
        float w1 = __int_as_float(e1.y);
        acc_edge(acc0, v0, pk2(w0, w0));
        acc_edge(acc1, v1, pk2(w1, w1));
    }
    if (i < c) {
        int2 e0 = bk[i];
        uint4 v0 = p4[(size_t)e0.x * 8 + part];
        float w0 = __int_as_float(e0.y);
        acc_edge(acc0, v0, pk2(w0, w0));
    }

    // Overflow path: never taken for this dataset, keeps correctness
    // unconditional for any degree distribution.
    if (craw > CAP) {
        int m = g_cnt[MAX_NODES];
        if (m > OVF_CAP) m = OVF_CAP;
        for (int j = 0; j < m; j++) {
            int e = g_ovf_list[j];
            if (dst[e] == n) {
                float we = w[e];
                uint4 v = p4[(size_t)src[e] * 8 + part];
                acc_edge(acc0, v, pk2(we, we));
            }
        }
    }

    float r[8];
    #pragma unroll
    for (int q = 0; q < 4; q++) {
        float lo0, hi0, lo1, hi1;
        upk2(lo0, hi0, acc0[q]);
        upk2(lo1, hi1, acc1[q]);
        r[q * 2 + 0] = lo0 + lo1;
        r[q * 2 + 1] = hi0 + hi1;
    }
    float4* o4 = reinterpret_cast<float4*>(out + (size_t)n * D + part * 8);
    o4[0] = make_float4(r[0], r[1], r[2], r[3]);
    o4[1] = make_float4(r[4], r[5], r[6], r[7]);
}

// ---------------------------------------------------------------------------
// kernel_launch — graph-capturable, allocation-free.
// Fork: GEMM on s1 concurrent with memset(cnt)+fill on the main stream.
// Input order: src[E] i32, dst[E] i32, w[E] f32, data[N*64] f32,
//              theta[64*64] f32, num_nodes i32
// ---------------------------------------------------------------------------
extern "C" void kernel_launch(void* const* d_in, const int* in_sizes, int n_in,
                              void* d_out, int out_size)
{
    const int*   src   = (const int*)  d_in[0];
    const int*   dst   = (const int*)  d_in[1];
    const float* w     = (const float*)d_in[2];
    const float* data  = (const float*)d_in[3];
    const float* theta = (const float*)d_in[4];

    const int E = in_sizes[0];
    const int N = in_sizes[3] / D;

    float* out = (float*)d_out;

    static __half* proj_ptr = nullptr;
    static int*    cnt_ptr  = nullptr;
    static cudaStream_t s1 = nullptr;
    static cudaEvent_t evFork = nullptr, evJoin = nullptr;
    if (!proj_ptr) {
        void* p = nullptr;
        cudaGetSymbolAddress(&p, g_projh); proj_ptr = (__half*)p;
        cudaGetSymbolAddress(&p, g_cnt);   cnt_ptr  = (int*)p;
        cudaStreamCreateWithFlags(&s1, cudaStreamNonBlocking);
        cudaEventCreateWithFlags(&evFork, cudaEventDisableTiming);
        cudaEventCreateWithFlags(&evJoin, cudaEventDisableTiming);
    }

    // Fork: GEMM on s1 (independent of the edge arrays).
    cudaEventRecord(evFork, 0);
    cudaStreamWaitEvent(s1, evFork, 0);
    int gemmBlocks = (N + 63) / 64;
    proj_kernel<<<gemmBlocks, 256, 0, s1>>>(data, theta, proj_ptr, N);
    cudaEventRecord(evJoin, s1);

    // Main stream: reset counters (+ ovf counter), build buckets.
    cudaMemsetAsync(cnt_ptr, 0, (size_t)(MAX_NODES + 1) * sizeof(int), 0);
    int fillBlocks = (E + 255) / 256;
    fill_kernel<<<fillBlocks, 256>>>(src, dst, w, E);

    // Join, then gather-reduce (writes every output row; no out memset).
    cudaStreamWaitEvent(0, evJoin, 0);
    long long gthreads = (long long)N * 8;
    int gatherBlocks = (int)((gthreads + 255) / 256);
    gather_kernel<<<gatherBlocks, 256>>>(src, dst, w, out, N);
}